// round 15
// baseline (speedup 1.0000x reference)
#include <cuda_runtime.h>
#include <cstdint>

// image [B=4, C=1, D=128, H=256, W=256] fp32
// out   [B, 2, D, H, W]: ch0 = copy, ch1 = sqrt(Gx^2+Gy^2+Gz^2 + 1e-8)
#define DIM_D 128
#define DIM_H 256
#define DIM_W 256
#define PLANE (DIM_H * DIM_W)
#define DCHUNK 64
#define ROW_F 144                   // floats per staged row (34 f4 used + pad)
#define BUF_F (3 * ROW_F)           // one plane buffer per warp: 3 rows
#define WARP_F (3 * BUF_F)          // 3 rotating buffers per warp
// total smem: 4 warps * WARP_F * 4B = 20736 B

__device__ __forceinline__ void cp16(uint32_t saddr, const float* gp) {
    asm volatile("cp.async.ca.shared.global [%0], [%1], 16;" :: "r"(saddr), "l"(gp));
}
__device__ __forceinline__ void st16z(uint32_t saddr) {
    asm volatile("st.shared.v4.b32 [%0], {%1, %1, %1, %1};" :: "r"(saddr), "r"(0) : "memory");
}
__device__ __forceinline__ void cp_commit() { asm volatile("cp.async.commit_group;"); }
__device__ __forceinline__ void cp_wait1()  { asm volatile("cp.async.wait_group 1;" ::: "memory"); }
__device__ __forceinline__ void cp_wait2()  { asm volatile("cp.async.wait_group 2;" ::: "memory"); }

// Single-instruction approximate sqrt (MUFU.SQRT), ~1 ulp: fine vs 1e-3 tol.
__device__ __forceinline__ float sqrt_fast(float x) {
    float r; asm("sqrt.approx.f32 %0, %1;" : "=f"(r) : "f"(x)); return r;
}

// Fold one lane-private staged plane into separable partials.
// sRow0 = this lane's float4 in row 0 of the buffer; rows at +ROW_F.
// Halo floats: interior lanes via shuffle; boundary lanes from their own
// staged halo chunk (zero-filled at image edges -> uniform handling).
//   A = s_h*s_w(x) (Gz=d_d(A)); B = s_h*d_w(x) (Gx=s_d(B)); C = d_h*s_w(x) (Gy=s_d(C))
__device__ __forceinline__ void fold_priv(
    const float* __restrict__ sRow0, int lane,
    float4& A, float4& B, float4& C, float4* cen)
{
    A = make_float4(0.f, 0.f, 0.f, 0.f);
    B = A; C = A;
#pragma unroll
    for (int r = 0; r < 3; r++) {
        const float* row = sRow0 + r * ROW_F;
        const float4 c = *reinterpret_cast<const float4*>(row);

        float xl = __shfl_up_sync(0xffffffffu, c.w, 1);
        if (lane == 0)  xl = row[-1];   // own staged halo chunk (0 at image edge)
        float xr = __shfl_down_sync(0xffffffffu, c.x, 1);
        if (lane == 31) xr = row[4];    // own staged halo chunk (0 at image edge)

        if (r == 1 && cen) *cen = c;

        float4 u, v;
        u.x = fmaf(2.f, c.x, xl  + c.y);
        u.y = fmaf(2.f, c.y, c.x + c.z);
        u.z = fmaf(2.f, c.z, c.y + c.w);
        u.w = fmaf(2.f, c.w, c.z + xr);
        v.x = c.y - xl;
        v.y = c.z - c.x;
        v.z = c.w - c.y;
        v.w = xr  - c.z;

        if (r == 1) {
            A.x = fmaf(2.f, u.x, A.x); A.y = fmaf(2.f, u.y, A.y);
            A.z = fmaf(2.f, u.z, A.z); A.w = fmaf(2.f, u.w, A.w);
            B.x = fmaf(2.f, v.x, B.x); B.y = fmaf(2.f, v.y, B.y);
            B.z = fmaf(2.f, v.z, B.z); B.w = fmaf(2.f, v.w, B.w);
        } else {
            const float dh = (r == 0) ? -1.f : 1.f;
            A.x += u.x; A.y += u.y; A.z += u.z; A.w += u.w;
            B.x += v.x; B.y += v.y; B.z += v.z; B.w += v.w;
            C.x = fmaf(dh, u.x, C.x); C.y = fmaf(dh, u.y, C.y);
            C.z = fmaf(dh, u.z, C.z); C.w = fmaf(dh, u.w, C.w);
        }
    }
}

__global__ void __launch_bounds__(128, 8)
sobel_edge_kernel(const float* __restrict__ img, float* __restrict__ out)
{
    __shared__ float sbuf[4 * WARP_F];   // 20.7 KB; per-warp, lane-private chunks

    const int tx    = threadIdx.x;          // 0..63 -> w (float4)
    const int ty    = threadIdx.y;          // 0..1  -> h row
    const int lane  = tx & 31;
    const int xhalf = tx >> 5;               // which w-half this warp covers
    const int warp  = ty * 2 + xhalf;        // 0..3
    const int W0    = xhalf * 128;            // warp's w origin
    const int w0    = tx * 4;                  // this lane's w (= W0 + lane*4)
    const int h0    = blockIdx.x * 2;
    const int h     = h0 + ty;                 // this warp's output row
    const int d0    = blockIdx.y * DCHUNK;
    const int b     = blockIdx.z;

    const float* gbase = img + (size_t)b * (DIM_D * PLANE);

    const uint32_t sB0   = (uint32_t)__cvta_generic_to_shared(&sbuf[0]);
    const uint32_t wbyte = sB0 + (uint32_t)warp * (WARP_F * 4u);

    // lane's main-chunk byte offset within a row: halo chunk at 0, main at 16+lane*16
    const uint32_t mainoff = 16u + (uint32_t)lane * 16u;
    const bool is_hl = (lane == 0),  hl_valid = (W0 > 0);            // left halo chunk
    const bool is_hr = (lane == 31), hr_valid = (W0 + 128) < DIM_W;  // right halo chunk

    // Stage plane p into this warp's buffer s. Lane-private: each lane copies
    // exactly the chunks it will read. Zero-fills out-of-range. Always commits.
    auto stage = [&](int s, int p, bool need) {
        if (need) {
            const bool pv = (p >= 0) && (p < DIM_D);
            const float* gplane = gbase + (size_t)p * PLANE;
            const uint32_t bufb = wbyte + (uint32_t)s * (BUF_F * 4u);
#pragma unroll
            for (int r = 0; r < 3; r++) {
                const int gh = h - 1 + r;
                const bool rv = pv && (gh >= 0) && (gh < DIM_H);
                const float* gRow = gplane + (size_t)gh * DIM_W + W0;
                const uint32_t rowb = bufb + (uint32_t)r * (ROW_F * 4u);
                // main chunk (w0 .. w0+3)
                if (rv) cp16(rowb + mainoff, gRow + lane * 4);
                else    st16z(rowb + mainoff);
                // halo chunks (boundary lanes only)
                if (is_hl) {
                    if (rv && hl_valid) cp16(rowb, gRow - 4);
                    else                st16z(rowb);
                } else if (is_hr) {
                    if (rv && hr_valid) cp16(rowb + 16u + 32u * 16u, gRow + 128);
                    else                st16z(rowb + 16u + 32u * 16u);
                }
            }
        }
        cp_commit();
    };

    // Output pointers
    float* o0 = out + (size_t)b * 2 * (DIM_D * PLANE)
              + (size_t)d0 * PLANE + (size_t)h * DIM_W + w0;   // copy ch, plane d0
    float* o1 = o0 + (size_t)(DIM_D * PLANE);                  // mag ch, plane d0

    // this lane's float4 in row 0 of buffer 0 (generic pointer for LDS)
    const float* sMy = sbuf + warp * WARP_F + 4 + lane * 4;

    float4 A0, B0, C0, A1, B1, C1, A2, B2, C2, cen;

    // --- prologue: stage planes d0-1, d0, d0+1 into bufs 0,1,2 (no barriers) ---
    stage(0, d0 - 1, true);
    stage(1, d0,     true);
    stage(2, d0 + 1, true);
    cp_wait2();                                           // buf0 ready (own copies)
    fold_priv(sMy, lane, A1, B1, C1, nullptr);            // plane d0-1
    cp_wait1();                                           // buf1 ready
    fold_priv(sMy + BUF_F, lane, A2, B2, C2, &cen);       // plane d0
    __stcs(reinterpret_cast<float4*>(o0), cen);           // copy(d0)
    o0 += PLANE;                                          // -> plane d0+1

    int sw = 0;   // write buffer for this iter
    int sr = 2;   // read (fold) buffer for this iter

#pragma unroll 3
    for (int dd = 0; dd < DCHUNK; dd++) {
        // (1) stage plane d0+dd+2 into buf sw (not needed on last iter)
        stage(sw, d0 + dd + 2, dd < DCHUNK - 1);

        // (2) wait for own copies of plane d0+dd+1; fold it (lane-private: no barrier)
        cp_wait1();
        A0 = A1; B0 = B1; C0 = C1;
        A1 = A2; B1 = B2; C1 = C2;
        fold_priv(sMy + sr * BUF_F, lane, A2, B2, C2, &cen);
        if (dd < DCHUNK - 1) {                    // copy(d0+dd+1) owned by this chunk
            __stcs(reinterpret_cast<float4*>(o0), cen);
        }
        o0 += PLANE;

        // (3) magnitude for plane d0+dd (approx sqrt: 1 MUFU per element)
        float4 gx, gy, gz, m;
        gx.x = fmaf(2.f, B1.x, B0.x + B2.x);
        gx.y = fmaf(2.f, B1.y, B0.y + B2.y);
        gx.z = fmaf(2.f, B1.z, B0.z + B2.z);
        gx.w = fmaf(2.f, B1.w, B0.w + B2.w);
        gy.x = fmaf(2.f, C1.x, C0.x + C2.x);
        gy.y = fmaf(2.f, C1.y, C0.y + C2.y);
        gy.z = fmaf(2.f, C1.z, C0.z + C2.z);
        gy.w = fmaf(2.f, C1.w, C0.w + C2.w);
        gz.x = A2.x - A0.x;
        gz.y = A2.y - A0.y;
        gz.z = A2.z - A0.z;
        gz.w = A2.w - A0.w;
        m.x = sqrt_fast(fmaf(gx.x, gx.x, fmaf(gy.x, gy.x, fmaf(gz.x, gz.x, 1e-8f))));
        m.y = sqrt_fast(fmaf(gx.y, gx.y, fmaf(gy.y, gy.y, fmaf(gz.y, gz.y, 1e-8f))));
        m.z = sqrt_fast(fmaf(gx.z, gx.z, fmaf(gy.z, gy.z, fmaf(gz.z, gz.z, 1e-8f))));
        m.w = sqrt_fast(fmaf(gx.w, gx.w, fmaf(gy.w, gy.w, fmaf(gz.w, gz.w, 1e-8f))));

        __stcs(reinterpret_cast<float4*>(o1), m);
        o1 += PLANE;

        // advance buffer ring (constant after unroll-3 copy propagation)
        sw = (sw == 2) ? 0 : sw + 1;
        sr = (sr == 2) ? 0 : sr + 1;
    }
}

extern "C" void kernel_launch(void* const* d_in, const int* in_sizes, int n_in,
                              void* d_out, int out_size)
{
    const float* img = (const float*)d_in[0];
    float* out = (float*)d_out;

    dim3 block(64, 2, 1);                        // 128 threads = 4 decoupled warps
    dim3 grid(DIM_H / 2, DIM_D / DCHUNK, 4);     // 128 x 2 x 4 = 1024 CTAs (1 wave @8/SM)

    sobel_edge_kernel<<<grid, block>>>(img, out);
}

// round 16
// speedup vs baseline: 1.3306x; 1.3306x over previous
#include <cuda_runtime.h>
#include <cstdint>

// image [B=4, C=1, D=128, H=256, W=256] fp32
// out   [B, 2, D, H, W]: ch0 = copy, ch1 = sqrt(Gx^2+Gy^2+Gz^2 + 1e-8)
#define DIM_D 128
#define DIM_H 256
#define DIM_W 256
#define PLANE (DIM_H * DIM_W)
#define DCHUNK 64
#define NROWS 4                     // rows h0-1 .. h0+2 staged per plane
#define STAGE_F (NROWS * DIM_W)     // 1024 floats = 4 KB per buffer

// .cg = global->L2->smem, no L1 allocation (16B only). Staged data is never
// re-read through L1, so .ca's L1 fill is pure wavefront/capacity waste.
__device__ __forceinline__ void cp16(uint32_t saddr, const float* gp) {
    asm volatile("cp.async.cg.shared.global [%0], [%1], 16;" :: "r"(saddr), "l"(gp));
}
__device__ __forceinline__ void cp_commit() { asm volatile("cp.async.commit_group;"); }
__device__ __forceinline__ void cp_wait1()  { asm volatile("cp.async.wait_group 1;" ::: "memory"); }
__device__ __forceinline__ void cp_wait2()  { asm volatile("cp.async.wait_group 2;" ::: "memory"); }

// Single-instruction approximate sqrt (MUFU.SQRT), ~1 ulp: fine vs 1e-3 tol.
__device__ __forceinline__ float sqrt_fast(float x) {
    float r; asm("sqrt.approx.f32 %0, %1;" : "=f"(r) : "f"(x)); return r;
}

// Fold one staged plane (smem) into separable partials for this thread's row.
// Halos via warp shuffle; only warp-boundary lanes touch smem.
//   A = s_h*s_w(x) (Gz=d_d(A)); B = s_h*d_w(x) (Gx=s_d(B)); C = d_h*s_w(x) (Gy=s_d(C))
__device__ __forceinline__ void fold_smem(
    const float* __restrict__ sB,   // &sbuf[s][ty*DIM_W + w0]
    int lane, bool edge_l, bool edge_r,
    float4& A, float4& B, float4& C, float4* cen)
{
    A = make_float4(0.f, 0.f, 0.f, 0.f);
    B = A; C = A;
#pragma unroll
    for (int r = 0; r < 3; r++) {
        const float* row = sB + r * DIM_W;
        const float4 c = *reinterpret_cast<const float4*>(row);

        float xl = __shfl_up_sync(0xffffffffu, c.w, 1);
        if (lane == 0)  xl = edge_l ? 0.f : row[-1];
        float xr = __shfl_down_sync(0xffffffffu, c.x, 1);
        if (lane == 31) xr = edge_r ? 0.f : row[4];

        if (r == 1 && cen) *cen = c;

        float4 u, v;
        u.x = fmaf(2.f, c.x, xl  + c.y);
        u.y = fmaf(2.f, c.y, c.x + c.z);
        u.z = fmaf(2.f, c.z, c.y + c.w);
        u.w = fmaf(2.f, c.w, c.z + xr);
        v.x = c.y - xl;
        v.y = c.z - c.x;
        v.z = c.w - c.y;
        v.w = xr  - c.z;

        if (r == 1) {
            A.x = fmaf(2.f, u.x, A.x); A.y = fmaf(2.f, u.y, A.y);
            A.z = fmaf(2.f, u.z, A.z); A.w = fmaf(2.f, u.w, A.w);
            B.x = fmaf(2.f, v.x, B.x); B.y = fmaf(2.f, v.y, B.y);
            B.z = fmaf(2.f, v.z, B.z); B.w = fmaf(2.f, v.w, B.w);
        } else {
            const float dh = (r == 0) ? -1.f : 1.f;
            A.x += u.x; A.y += u.y; A.z += u.z; A.w += u.w;
            B.x += v.x; B.y += v.y; B.z += v.z; B.w += v.w;
            C.x = fmaf(dh, u.x, C.x); C.y = fmaf(dh, u.y, C.y);
            C.z = fmaf(dh, u.z, C.z); C.w = fmaf(dh, u.w, C.w);
        }
    }
}

__global__ void __launch_bounds__(128, 8)
sobel_edge_kernel(const float* __restrict__ img, float* __restrict__ out)
{
    __shared__ float sbuf[3][STAGE_F];   // 12 KB

    const int tx  = threadIdx.x;           // 0..63 -> w (float4)
    const int ty  = threadIdx.y;           // 0..1  -> h row
    const int tid = tx + ty * 64;           // 0..127
    const int lane = tx & 31;
    const int w0  = tx * 4;
    const int h0  = blockIdx.x * 2;
    const int h   = h0 + ty;
    const int d0  = blockIdx.y * DCHUNK;
    const int b   = blockIdx.z;

    // Warp covers tx [0..31] or [32..63]; boundary lanes are at the image
    // edge only for tx==0 (left) / tx==63 (right).
    const bool edge_l = (tx & 32) == 0;    // warp lane0 at w0==0
    const bool edge_r = (tx & 32) != 0;    // warp lane31 at w0==252

    const float* gbase = img + (size_t)b * (DIM_D * PLANE);

    // staging: 256 16B chunks (4 rows x 64 float4) per plane, 128 threads x 2
    const int r0 = tid >> 6,          c0 = tid & 63;          // rows 0,1
    const int r1 = (tid + 128) >> 6,  c1 = (tid + 128) & 63;  // rows 2,3
    const int g0 = h0 - 1 + r0;
    const int g1 = h0 - 1 + r1;
    const bool gv0 = (g0 >= 0) && (g0 < DIM_H);
    const bool gv1 = (g1 >= 0) && (g1 < DIM_H);
    const float* gr0 = gbase + (size_t)g0 * DIM_W + c0 * 4;   // + p*PLANE at use
    const float* gr1 = gbase + (size_t)g1 * DIM_W + c1 * 4;
    const uint32_t sB0 = (uint32_t)__cvta_generic_to_shared(&sbuf[0][0]);
    const uint32_t so0 = (uint32_t)(r0 * DIM_W + c0 * 4) * 4u;
    const uint32_t so1 = (uint32_t)(r1 * DIM_W + c1 * 4) * 4u;
    float* z0 = &sbuf[0][r0 * DIM_W + c0 * 4];  // generic ptrs for zero-fill
    float* z1 = &sbuf[0][r1 * DIM_W + c1 * 4];

    const float4 f4z = make_float4(0.f, 0.f, 0.f, 0.f);

    // Stage plane p into buffer s (zero-fills invalid plane/rows). Always commits.
    auto stage = [&](int s, int p, bool need) {
        if (need) {
            const bool pv = (p >= 0) && (p < DIM_D);
            const size_t poff = (size_t)p * PLANE;
            const uint32_t sbase = sB0 + (uint32_t)s * (STAGE_F * 4u);
            if (pv && gv0) cp16(sbase + so0, gr0 + poff);
            else *reinterpret_cast<float4*>(z0 + s * STAGE_F) = f4z;
            if (pv && gv1) cp16(sbase + so1, gr1 + poff);
            else *reinterpret_cast<float4*>(z1 + s * STAGE_F) = f4z;
        }
        cp_commit();
    };

    // Output pointers
    float* o0 = out + (size_t)b * 2 * (DIM_D * PLANE)
              + (size_t)d0 * PLANE + (size_t)h * DIM_W + w0;   // copy ch, plane d0
    float* o1 = o0 + (size_t)(DIM_D * PLANE);                  // mag ch, plane d0
    const float* sMy = &sbuf[0][ty * DIM_W + w0];              // fold window, buf0

    float4 A0, B0, C0, A1, B1, C1, A2, B2, C2, cen;

    // --- prologue: stage planes d0-1, d0, d0+1 into bufs 0,1,2 ---
    stage(0, d0 - 1, true);
    stage(1, d0,     true);
    stage(2, d0 + 1, true);
    cp_wait2();
    __syncthreads();
    fold_smem(sMy, lane, edge_l, edge_r, A1, B1, C1, nullptr);            // d0-1
    cp_wait1();
    __syncthreads();
    fold_smem(sMy + STAGE_F, lane, edge_l, edge_r, A2, B2, C2, &cen);     // d0
    __stcs(reinterpret_cast<float4*>(o0), cen);                           // copy(d0)
    o0 += PLANE;                                                          // -> d0+1

    int sw = 0;   // write buffer for this iter
    int sr = 2;   // read (fold) buffer for this iter

#pragma unroll 3
    for (int dd = 0; dd < DCHUNK; dd++) {
        // (1) stage plane d0+dd+2 into buf sw (not needed on last iter)
        stage(sw, d0 + dd + 2, dd < DCHUNK - 1);

        // (2) wait for plane d0+dd+1 (committed 2 groups ago), sync, fold it
        cp_wait1();
        __syncthreads();
        A0 = A1; B0 = B1; C0 = C1;
        A1 = A2; B1 = B2; C1 = C2;
        fold_smem(&sbuf[sr][ty * DIM_W + w0], lane, edge_l, edge_r, A2, B2, C2, &cen);
        if (dd < DCHUNK - 1) {                    // copy(d0+dd+1) owned by this chunk
            __stcs(reinterpret_cast<float4*>(o0), cen);
        }
        o0 += PLANE;

        // (3) magnitude for plane d0+dd (approx sqrt: 1 MUFU per element)
        float4 gx, gy, gz, m;
        gx.x = fmaf(2.f, B1.x, B0.x + B2.x);
        gx.y = fmaf(2.f, B1.y, B0.y + B2.y);
        gx.z = fmaf(2.f, B1.z, B0.z + B2.z);
        gx.w = fmaf(2.f, B1.w, B0.w + B2.w);
        gy.x = fmaf(2.f, C1.x, C0.x + C2.x);
        gy.y = fmaf(2.f, C1.y, C0.y + C2.y);
        gy.z = fmaf(2.f, C1.z, C0.z + C2.z);
        gy.w = fmaf(2.f, C1.w, C0.w + C2.w);
        gz.x = A2.x - A0.x;
        gz.y = A2.y - A0.y;
        gz.z = A2.z - A0.z;
        gz.w = A2.w - A0.w;
        m.x = sqrt_fast(fmaf(gx.x, gx.x, fmaf(gy.x, gy.x, fmaf(gz.x, gz.x, 1e-8f))));
        m.y = sqrt_fast(fmaf(gx.y, gx.y, fmaf(gy.y, gy.y, fmaf(gz.y, gz.y, 1e-8f))));
        m.z = sqrt_fast(fmaf(gx.z, gx.z, fmaf(gy.z, gy.z, fmaf(gz.z, gz.z, 1e-8f))));
        m.w = sqrt_fast(fmaf(gx.w, gx.w, fmaf(gy.w, gy.w, fmaf(gz.w, gz.w, 1e-8f))));

        __stcs(reinterpret_cast<float4*>(o1), m);
        o1 += PLANE;

        // advance buffer ring (constant after unroll-3 copy propagation)
        sw = (sw == 2) ? 0 : sw + 1;
        sr = (sr == 2) ? 0 : sr + 1;
    }
}

extern "C" void kernel_launch(void* const* d_in, const int* in_sizes, int n_in,
                              void* d_out, int out_size)
{
    const float* img = (const float*)d_in[0];
    float* out = (float*)d_out;

    dim3 block(64, 2, 1);                        // 128 threads
    dim3 grid(DIM_H / 2, DIM_D / DCHUNK, 4);     // 128 x 2 x 4 = 1024 CTAs (1 wave @8/SM)

    sobel_edge_kernel<<<grid, block>>>(img, out);
}